// round 12
// baseline (speedup 1.0000x reference)
#include <cuda_runtime.h>
#include <math.h>
#include <stdint.h>

#define BB 4
#define NN 2048
#define DD 512
#define HH 8
#define EE 512
#define DD1 1024
#define HDD 128
#define MROWS (BB*NN)

// ---------------- scratch (device globals; no allocation allowed) ----------------
__device__ float g_xn[MROWS*DD];
__device__ float g_u[MROWS*DD1];
__device__ float g_v[MROWS*DD1];     // [b][h][n][hd]
__device__ float g_y[MROWS*DD1];
__device__ float g_h1[NN*EE];
__device__ float g_t1[NN*EE];
__device__ float g_a[HH*NN*HDD];     // [h][k][hd]
// transposed weights [N][K] fp32 (pre-rounded to tf32)
__device__ float g_WuvT[2*DD1*DD];   // Wu rows 0..1023, Wv rows 1024..2047
__device__ float g_WoT[DD*DD1];
__device__ float g_W1T[EE*EE];
__device__ float g_W2T[EE*EE];
__device__ float g_W3T[EE*EE];
__device__ float g_WzT[DD1*EE];

// ---------------- helpers ----------------
__device__ __forceinline__ uint32_t smem_u32(const void* p) {
    uint32_t a;
    asm("{ .reg .u64 t; cvta.to.shared.u64 t, %1; cvt.u32.u64 %0, t; }" : "=r"(a) : "l"(p));
    return a;
}
__device__ __forceinline__ float rtf(float f) {
    uint32_t r; asm("cvt.rna.tf32.f32 %0, %1;" : "=r"(r) : "f"(f));
    return __uint_as_float(r);
}
__device__ __forceinline__ void fma2(float2& d, float2 a, float2 b) {
    unsigned long long ud = *reinterpret_cast<unsigned long long*>(&d);
    unsigned long long ua = *reinterpret_cast<unsigned long long*>(&a);
    unsigned long long ub = *reinterpret_cast<unsigned long long*>(&b);
    asm("fma.rn.f32x2 %0, %1, %2, %0;" : "+l"(ud) : "l"(ua), "l"(ub));
    d = *reinterpret_cast<float2*>(&ud);
}
__device__ __forceinline__ void mma_tf32(float* c, const uint32_t* a, const uint32_t* b) {
    asm volatile(
        "mma.sync.aligned.m16n8k8.row.col.f32.tf32.tf32.f32 "
        "{%0,%1,%2,%3}, {%4,%5,%6,%7}, {%8,%9}, {%0,%1,%2,%3};"
        : "+f"(c[0]), "+f"(c[1]), "+f"(c[2]), "+f"(c[3])
        : "r"(a[0]), "r"(a[1]), "r"(a[2]), "r"(a[3]), "r"(b[0]), "r"(b[1]));
}
__device__ __forceinline__ float silu_fast(float x) {
    return x / (1.0f + __expf(-x));
}

// ---------------- srms (cols fixed 512), optional relu; output rounded to tf32 ----------------
__global__ void rms_kernel(const float* __restrict__ in, float* __restrict__ out, int relu_flag) {
    int row = blockIdx.x;
    float4 val = reinterpret_cast<const float4*>(in)[(size_t)row*128 + threadIdx.x];
    float ss = val.x*val.x + val.y*val.y + val.z*val.z + val.w*val.w;
    #pragma unroll
    for (int o = 16; o > 0; o >>= 1) ss += __shfl_xor_sync(0xffffffffu, ss, o);
    __shared__ float ws[4];
    if ((threadIdx.x & 31) == 0) ws[threadIdx.x >> 5] = ss;
    __syncthreads();
    float tot = ws[0] + ws[1] + ws[2] + ws[3];
    float inv = 1.0f / (sqrtf(tot * (1.0f/512.0f)) + 1e-8f);
    val.x *= inv; val.y *= inv; val.z *= inv; val.w *= inv;
    if (relu_flag) {
        val.x = fmaxf(val.x, 0.f); val.y = fmaxf(val.y, 0.f);
        val.z = fmaxf(val.z, 0.f); val.w = fmaxf(val.w, 0.f);
    }
    val.x = rtf(val.x); val.y = rtf(val.y); val.z = rtf(val.z); val.w = rtf(val.w);
    reinterpret_cast<float4*>(out)[(size_t)row*128 + threadIdx.x] = val;
}

// ---------------- fused: hcf row init + srms + relu + tf32 round ----------------
__global__ void posrms_kernel(const float* __restrict__ Wp, const float* __restrict__ bp,
                              float* __restrict__ out) {
    int n = blockIdx.x;
    int e = threadIdx.x * 4;
    float4 w = *reinterpret_cast<const float4*>(Wp + e);
    float4 b = *reinterpret_cast<const float4*>(bp + e);
    float fn = (float)n;
    float4 val;
    val.x = fn*w.x + b.x; val.y = fn*w.y + b.y; val.z = fn*w.z + b.z; val.w = fn*w.w + b.w;
    float ss = val.x*val.x + val.y*val.y + val.z*val.z + val.w*val.w;
    #pragma unroll
    for (int o = 16; o > 0; o >>= 1) ss += __shfl_xor_sync(0xffffffffu, ss, o);
    __shared__ float ws[4];
    if ((threadIdx.x & 31) == 0) ws[threadIdx.x >> 5] = ss;
    __syncthreads();
    float tot = ws[0] + ws[1] + ws[2] + ws[3];
    float inv = 1.0f / (sqrtf(tot * (1.0f/512.0f)) + 1e-8f);
    val.x = rtf(fmaxf(val.x*inv, 0.f)); val.y = rtf(fmaxf(val.y*inv, 0.f));
    val.z = rtf(fmaxf(val.z*inv, 0.f)); val.w = rtf(fmaxf(val.w*inv, 0.f));
    reinterpret_cast<float4*>(out)[(size_t)n*128 + threadIdx.x] = val;
}

// ---------------- fused transpose of all 7 weights: out[n][k] = tf32(in[k][n]) ----------------
__global__ void transpose_all_kernel(
    const float* __restrict__ Wu, const float* __restrict__ Wv, const float* __restrict__ Wo,
    const float* __restrict__ W1, const float* __restrict__ W2, const float* __restrict__ W3,
    const float* __restrict__ Wz)
{
    __shared__ float t[32][33];
    int z = blockIdx.z;
    const float* in; float* out; int K, N;
    switch (z) {
        case 0: in = Wu; out = g_WuvT;            K = DD;  N = DD1; break;
        case 1: in = Wv; out = g_WuvT + DD1*DD;   K = DD;  N = DD1; break;
        case 2: in = Wo; out = g_WoT;             K = DD1; N = DD;  break;
        case 3: in = W1; out = g_W1T;             K = EE;  N = EE;  break;
        case 4: in = W2; out = g_W2T;             K = EE;  N = EE;  break;
        case 5: in = W3; out = g_W3T;             K = EE;  N = EE;  break;
        default: in = Wz; out = g_WzT;            K = EE;  N = DD1; break;
    }
    if ((int)blockIdx.x * 32 >= N || (int)blockIdx.y * 32 >= K) return;
    int n0 = blockIdx.x * 32, k0 = blockIdx.y * 32;
    int tx = threadIdx.x, ty = threadIdx.y;   // 32 x 8
    #pragma unroll
    for (int i = 0; i < 32; i += 8)
        t[ty + i][tx] = rtf(in[(size_t)(k0 + ty + i) * N + n0 + tx]);
    __syncthreads();
    #pragma unroll
    for (int i = 0; i < 32; i += 8)
        out[(size_t)(n0 + ty + i) * K + k0 + tx] = t[tx][ty + i];
}

// ---------------- mma.sync tf32 GEMM, 2-stage cp.async pipeline ----------------
// C(MxN) = A(MxK) @ Bt(NxK)^T + bias; tile 128x128, BK=32, 256 thr, warp tile 64x32
// act: 0 none, 1 silu
// smode: 0 plain; 2 coef->g_a decay; 3 +resid; 4 fused u|v (c<1024 u, else v)
#define TGBK 32
#define TILEF (128*TGBK)          // floats per tile buffer
#define TG_SMEM (4*TILEF*4)       // 2 stages x (A+B) = 65536 bytes

__global__ void __launch_bounds__(256, 2) tgemm_kernel(
    const float* __restrict__ A, const float* __restrict__ Bt,
    const float* __restrict__ bias, const float* __restrict__ bias2,
    float* __restrict__ C,
    int M, int Nc, int K, int act, int smode, const float* __restrict__ resid)
{
    extern __shared__ float smf[];
    float* AsBase = smf;              // [2][TILEF] swizzled
    float* BsBase = smf + 2*TILEF;
    int tid = threadIdx.x;
    int wid = tid >> 5, lane = tid & 31;
    int gid = lane >> 2, tc = lane & 3;
    int m0 = (wid >> 2) * 64, n0 = (wid & 3) * 32;
    int bm = blockIdx.y * 128, bn = blockIdx.x * 128;

    float acc[4][4][4];
    #pragma unroll
    for (int mi = 0; mi < 4; mi++)
        #pragma unroll
        for (int ni = 0; ni < 4; ni++)
            #pragma unroll
            for (int q = 0; q < 4; q++) acc[mi][ni][q] = 0.f;

    const float* Abase = A  + (size_t)bm * K;
    const float* Bbase = Bt + (size_t)bn * K;

    #define LD_CHUNK(buf, k0v) do { \
        float* dA = AsBase + (buf)*TILEF; \
        float* dB = BsBase + (buf)*TILEF; \
        _Pragma("unroll") \
        for (int t_ = 0; t_ < 4; t_++) { \
            int j = tid + t_*256; \
            int row = j >> 3, c4 = j & 7; \
            int soff = row*32 + ((c4 ^ (row & 7)) << 2); \
            uint32_t da = smem_u32(dA + soff); \
            const float* sa = Abase + (size_t)row*K + (k0v) + (c4 << 2); \
            asm volatile("cp.async.cg.shared.global [%0], [%1], 16;" :: "r"(da), "l"(sa)); \
            uint32_t db = smem_u32(dB + soff); \
            const float* sb = Bbase + (size_t)row*K + (k0v) + (c4 << 2); \
            asm volatile("cp.async.cg.shared.global [%0], [%1], 16;" :: "r"(db), "l"(sb)); \
        } \
        asm volatile("cp.async.commit_group;"); \
    } while (0)

    int nch = K >> 5;
    LD_CHUNK(0, 0);
    for (int ch = 0; ch < nch; ch++) {
        if (ch + 1 < nch) {
            LD_CHUNK((ch + 1) & 1, (ch + 1) << 5);
            asm volatile("cp.async.wait_group 1;");
        } else {
            asm volatile("cp.async.wait_group 0;");
        }
        __syncthreads();
        const uint32_t* Au = (const uint32_t*)(AsBase + (ch & 1)*TILEF);
        const uint32_t* Bu = (const uint32_t*)(BsBase + (ch & 1)*TILEF);
        #pragma unroll
        for (int ks = 0; ks < 4; ks++) {
            int f0 = ks*2, f1 = f0 + 1;
            int x0 = (((f0 ^ gid) << 2) + tc);
            int x1 = (((f1 ^ gid) << 2) + tc);
            uint32_t af[4][4], bf[4][2];
            #pragma unroll
            for (int mi = 0; mi < 4; mi++) {
                int ra = (m0 + mi*16 + gid) * 32;
                int rb = ra + 8*32;
                af[mi][0] = Au[ra + x0]; af[mi][1] = Au[rb + x0];
                af[mi][2] = Au[ra + x1]; af[mi][3] = Au[rb + x1];
            }
            #pragma unroll
            for (int ni = 0; ni < 4; ni++) {
                int rn = (n0 + ni*8 + gid) * 32;
                bf[ni][0] = Bu[rn + x0];
                bf[ni][1] = Bu[rn + x1];
            }
            #pragma unroll
            for (int mi = 0; mi < 4; mi++)
                #pragma unroll
                for (int ni = 0; ni < 4; ni++)
                    mma_tf32(acc[mi][ni], af[mi], bf[ni]);
        }
        __syncthreads();
    }

    // epilogue
    #pragma unroll
    for (int mi = 0; mi < 4; mi++) {
        #pragma unroll
        for (int ni = 0; ni < 4; ni++) {
            #pragma unroll
            for (int half = 0; half < 2; half++) {
                int r = bm + m0 + mi*16 + gid + half*8;
                int c = bn + n0 + ni*8 + 2*tc;
                float2 val = make_float2(acc[mi][ni][half*2], acc[mi][ni][half*2 + 1]);
                float2 bi;
                if (smode == 4 && c >= DD1) bi = *reinterpret_cast<const float2*>(bias2 + (c - DD1));
                else                        bi = *reinterpret_cast<const float2*>(bias + c);
                val.x += bi.x; val.y += bi.y;
                if (act == 1) {
                    val.x = silu_fast(val.x);
                    val.y = silu_fast(val.y);
                }
                if (smode == 0) {
                    *reinterpret_cast<float2*>(C + (size_t)r * Nc + c) = val;
                } else if (smode == 4) {
                    if (c < DD1) {
                        *reinterpret_cast<float2*>(&g_u[(size_t)r * DD1 + c]) = val;
                    } else {
                        int cc = c - DD1;
                        int b_ = r >> 11, nt = r & (NN - 1);
                        int h_ = cc >> 7, hd = cc & (HDD - 1);
                        *reinterpret_cast<float2*>(&g_v[(((size_t)(b_*HH + h_))*NN + nt)*HDD + hd]) = val;
                    }
                } else if (smode == 2) {
                    float sc = (r == 0) ? 1.0f : __expf((float)r * (-1.0005003335835335e-3f));
                    int h_ = c >> 7, hd = c & (HDD - 1);
                    val.x *= sc; val.y *= sc;
                    *reinterpret_cast<float2*>(&g_a[((size_t)h_*NN + r)*HDD + hd]) = val;
                } else {
                    size_t o = (size_t)r * Nc + c;
                    float2 rr = *reinterpret_cast<const float2*>(resid + o);
                    val.x += rr.x; val.y += rr.y;
                    *reinterpret_cast<float2*>(C + o) = val;
                }
            }
        }
    }
}

// ---------------- causal conv: a-ring + cp.async 2-stage prefetch ----------------
// per (b,h), 256 thr, CTT=64 t-tile, CSC=32 s-chunks.
// a ring: 128 rows (slot = k & 127), only 32 new rows loaded per chunk.
// v: 2 x 32-row buffers. Inner loop identical to proven R3 version.
#define CSC 32
#define CTT 64
#define CONV_SMEM ((2*CSC*HDD + 128*HDD)*4)   // 32KB v + 64KB a = 98304 B

__global__ void __launch_bounds__(256, 2) conv_kernel(
    const float* __restrict__ vg, const float* __restrict__ ag,
    const float* __restrict__ ug, float* __restrict__ yg)
{
    extern __shared__ float sm[];
    float* v_sf = sm;                      // [2][CSC][HDD]
    float* a_sf = sm + 2*CSC*HDD;          // [128][HDD] ring
    float2* a_sh = reinterpret_cast<float2*>(a_sf);
    int bh = blockIdx.y;
    int b = bh >> 3, h = bh & 7;
    int t0 = (gridDim.x - 1 - blockIdx.x) * CTT;  // heavy tiles first
    int tid = threadIdx.x;
    int hdp = tid & 63;
    int tg  = tid >> 6;
    const float* vbase = vg + (size_t)bh * NN * HDD;
    const float* abase = ag + (size_t)h  * NN * HDD;
    float2 acc[16];
    #pragma unroll
    for (int i = 0; i < 16; i++) acc[i] = make_float2(0.f, 0.f);

    int nch = (t0 + CTT) / CSC;   // >= 2

    // issue loads for chunk c: v rows [32c,32c+32) into buf c&1; a new rows into ring
    #define CONV_ISSUE(c) do { \
        float* vdst = v_sf + ((c) & 1) * CSC * HDD; \
        const float* vsrc = vbase + (size_t)(c) * CSC * HDD; \
        _Pragma("unroll") \
        for (int i_ = 0; i_ < 4; i_++) { \
            int idx = tid + i_*256; \
            int row = idx >> 5, c4 = (idx & 31) << 2; \
            uint32_t dv = smem_u32(vdst + row*HDD + c4); \
            asm volatile("cp.async.cg.shared.global [%0], [%1], 16;" :: "r"(dv), "l"(vsrc + row*HDD + c4)); \
        } \
        int klo_ = t0 - 32*(c) - 31; \
        int nrows_ = ((c) == 0) ? 95 : 32; \
        for (int idx = tid; idx < nrows_*32; idx += 256) { \
            int j_ = idx >> 5, c4 = (idx & 31) << 2; \
            int k_ = klo_ + j_; \
            uint32_t da_ = smem_u32(a_sf + (k_ & 127)*HDD + c4); \
            if (k_ >= 0) { \
                asm volatile("cp.async.cg.shared.global [%0], [%1], 16;" :: "r"(da_), "l"(abase + (size_t)k_*HDD + c4)); \
            } else { \
                asm volatile("st.shared.v4.b32 [%0], {%1,%1,%1,%1};" :: "r"(da_), "r"(0u)); \
            } \
        } \
        asm volatile("cp.async.commit_group;"); \
    } while (0)

    CONV_ISSUE(0);
    for (int c = 0; c < nch; c++) {
        if (c + 1 < nch) {
            CONV_ISSUE(c + 1);
            asm volatile("cp.async.wait_group 1;");
        } else {
            asm volatile("cp.async.wait_group 0;");
        }
        __syncthreads();
        int s0 = c * CSC;
        const float2* vb = reinterpret_cast<const float2*>(v_sf + (c & 1)*CSC*HDD);
        #pragma unroll 1
        for (int sb = 0; sb < CSC; sb += 8) {
            float2 vr[8];
            #pragma unroll
            for (int q = 0; q < 8; q++) vr[q] = vb[(sb + q)*64 + hdp];
            int wk = t0 - s0 + tg*16 - sb - 7;   // absolute k of w[0]
            float2 w[8];
            #pragma unroll
            for (int q = 0; q < 8; q++) w[q] = a_sh[((wk + q) & 127)*64 + hdp];
            #pragma unroll
            for (int tl = 0; tl < 16; tl++) {
                #pragma unroll
                for (int q = 0; q < 8; q++) fma2(acc[tl], w[q], vr[7 - q]);
                #pragma unroll
                for (int q = 0; q < 7; q++) w[q] = w[q + 1];
                w[7] = a_sh[((wk + tl + 8) & 127)*64 + hdp];
            }
        }
        __syncthreads();
    }
    #pragma unroll
    for (int tl = 0; tl < 16; tl++) {
        int t = t0 + tg*16 + tl;
        size_t o = ((size_t)(b*NN + t))*DD1 + h*HDD + hdp*2;
        float2 uu = *reinterpret_cast<const float2*>(ug + o);
        float2 r = acc[tl];
        r.x = rtf(r.x * uu.x); r.y = rtf(r.y * uu.y);
        *reinterpret_cast<float2*>(yg + o) = r;
    }
}

// ---------------- launch ----------------
extern "C" void kernel_launch(void* const* d_in, const int* in_sizes, int n_in,
                              void* d_out, int out_size)
{
    const float* x  = (const float*)d_in[0];
    const float* Wu = (const float*)d_in[1];
    const float* bu = (const float*)d_in[2];
    const float* Wv = (const float*)d_in[3];
    const float* bv = (const float*)d_in[4];
    const float* Wo = (const float*)d_in[5];
    const float* bo = (const float*)d_in[6];
    const float* Wp = (const float*)d_in[7];
    const float* bp = (const float*)d_in[8];
    const float* W1 = (const float*)d_in[9];
    const float* b1 = (const float*)d_in[10];
    const float* W2 = (const float*)d_in[11];
    const float* b2 = (const float*)d_in[12];
    const float* W3 = (const float*)d_in[13];
    const float* b3 = (const float*)d_in[14];
    const float* Wz = (const float*)d_in[15];
    const float* bz = (const float*)d_in[16];
    float* out = (float*)d_out;

    float *xn, *u, *v, *y, *h1, *t1, *a;
    float *wuvt, *wot, *w1t, *w2t, *w3t, *wzt;
    cudaGetSymbolAddress((void**)&xn, g_xn);
    cudaGetSymbolAddress((void**)&u,  g_u);
    cudaGetSymbolAddress((void**)&v,  g_v);
    cudaGetSymbolAddress((void**)&y,  g_y);
    cudaGetSymbolAddress((void**)&h1, g_h1);
    cudaGetSymbolAddress((void**)&t1, g_t1);
    cudaGetSymbolAddress((void**)&a,  g_a);
    cudaGetSymbolAddress((void**)&wuvt, g_WuvT);
    cudaGetSymbolAddress((void**)&wot, g_WoT);
    cudaGetSymbolAddress((void**)&w1t, g_W1T);
    cudaGetSymbolAddress((void**)&w2t, g_W2T);
    cudaGetSymbolAddress((void**)&w3t, g_W3T);
    cudaGetSymbolAddress((void**)&wzt, g_WzT);

    cudaFuncSetAttribute(conv_kernel, cudaFuncAttributeMaxDynamicSharedMemorySize, CONV_SMEM);
    cudaFuncSetAttribute(tgemm_kernel, cudaFuncAttributeMaxDynamicSharedMemorySize, TG_SMEM);

    // launch #1
    transpose_all_kernel<<<dim3(32, 32, 7), dim3(32, 8)>>>(Wu, Wv, Wo, W1, W2, W3, Wz);
    // launch #2
    rms_kernel<<<MROWS, 128>>>(x, xn, 0);
    // launch #3
    posrms_kernel<<<NN, 128>>>(Wp, bp, t1);
    // launch #4: fused u|v GEMM (profiled slot)
    tgemm_kernel<<<dim3(2*DD1/128, MROWS/128), 256, TG_SMEM>>>(xn, wuvt, bu, bv, nullptr, MROWS, 2*DD1, DD, 1, 4, nullptr);

    tgemm_kernel<<<dim3(EE/128, NN/128), 256, TG_SMEM>>>(t1, w1t, b1, nullptr, h1, NN, EE, EE, 0, 0, nullptr);
    rms_kernel<<<NN, 128>>>(h1, t1, 1);
    tgemm_kernel<<<dim3(EE/128, NN/128), 256, TG_SMEM>>>(t1, w2t, b2, nullptr, h1, NN, EE, EE, 0, 0, nullptr);
    rms_kernel<<<NN, 128>>>(h1, t1, 1);
    tgemm_kernel<<<dim3(EE/128, NN/128), 256, TG_SMEM>>>(t1, w3t, b3, nullptr, h1, NN, EE, EE, 0, 0, nullptr);
    rms_kernel<<<NN, 128>>>(h1, t1, 1);
    tgemm_kernel<<<dim3(DD1/128, NN/128), 256, TG_SMEM>>>(t1, wzt, bz, nullptr, nullptr, NN, DD1, EE, 0, 2, nullptr);

    conv_kernel<<<dim3(NN/CTT, BB*HH), 256, CONV_SMEM>>>(v, a, u, y);

    tgemm_kernel<<<dim3(DD/128, MROWS/128), 256, TG_SMEM>>>(y, wot, bo, nullptr, out, MROWS, DD, DD1, 0, 3, x);
}

// round 16
// speedup vs baseline: 1.0515x; 1.0515x over previous
#include <cuda_runtime.h>
#include <math.h>
#include <stdint.h>

#define BB 4
#define NN 2048
#define DD 512
#define HH 8
#define EE 512
#define DD1 1024
#define HDD 128
#define MROWS (BB*NN)

// ---------------- scratch (device globals; no allocation allowed) ----------------
__device__ float g_xn[MROWS*DD];
__device__ float g_u[MROWS*DD1];
__device__ float g_v[MROWS*DD1];     // [b][h][n][hd]
__device__ float g_y[MROWS*DD1];
__device__ float g_h1[NN*EE];
__device__ float g_t1[NN*EE];
__device__ float g_a[HH*NN*HDD];     // [h][k][hd]
// transposed weights [N][K] fp32 (pre-rounded to tf32)
__device__ float g_WuvT[2*DD1*DD];   // Wu rows 0..1023, Wv rows 1024..2047
__device__ float g_WoT[DD*DD1];
__device__ float g_W1T[EE*EE];
__device__ float g_W2T[EE*EE];
__device__ float g_W3T[EE*EE];
__device__ float g_WzT[DD1*EE];

// ---------------- helpers ----------------
__device__ __forceinline__ uint32_t smem_u32(const void* p) {
    uint32_t a;
    asm("{ .reg .u64 t; cvta.to.shared.u64 t, %1; cvt.u32.u64 %0, t; }" : "=r"(a) : "l"(p));
    return a;
}
__device__ __forceinline__ float rtf(float f) {
    uint32_t r; asm("cvt.rna.tf32.f32 %0, %1;" : "=r"(r) : "f"(f));
    return __uint_as_float(r);
}
__device__ __forceinline__ void fma2(float2& d, float2 a, float2 b) {
    unsigned long long ud = *reinterpret_cast<unsigned long long*>(&d);
    unsigned long long ua = *reinterpret_cast<unsigned long long*>(&a);
    unsigned long long ub = *reinterpret_cast<unsigned long long*>(&b);
    asm("fma.rn.f32x2 %0, %1, %2, %0;" : "+l"(ud) : "l"(ua), "l"(ub));
    d = *reinterpret_cast<float2*>(&ud);
}
__device__ __forceinline__ void mma_tf32(float* c, const uint32_t* a, const uint32_t* b) {
    asm volatile(
        "mma.sync.aligned.m16n8k8.row.col.f32.tf32.tf32.f32 "
        "{%0,%1,%2,%3}, {%4,%5,%6,%7}, {%8,%9}, {%0,%1,%2,%3};"
        : "+f"(c[0]), "+f"(c[1]), "+f"(c[2]), "+f"(c[3])
        : "r"(a[0]), "r"(a[1]), "r"(a[2]), "r"(a[3]), "r"(b[0]), "r"(b[1]));
}
__device__ __forceinline__ float silu_fast(float x) {
    return x / (1.0f + __expf(-x));
}

// ---------------- srms (cols fixed 512), optional relu; output rounded to tf32 ----------------
__global__ void rms_kernel(const float* __restrict__ in, float* __restrict__ out, int relu_flag) {
    int row = blockIdx.x;
    float4 val = reinterpret_cast<const float4*>(in)[(size_t)row*128 + threadIdx.x];
    float ss = val.x*val.x + val.y*val.y + val.z*val.z + val.w*val.w;
    #pragma unroll
    for (int o = 16; o > 0; o >>= 1) ss += __shfl_xor_sync(0xffffffffu, ss, o);
    __shared__ float ws[4];
    if ((threadIdx.x & 31) == 0) ws[threadIdx.x >> 5] = ss;
    __syncthreads();
    float tot = ws[0] + ws[1] + ws[2] + ws[3];
    float inv = 1.0f / (sqrtf(tot * (1.0f/512.0f)) + 1e-8f);
    val.x *= inv; val.y *= inv; val.z *= inv; val.w *= inv;
    if (relu_flag) {
        val.x = fmaxf(val.x, 0.f); val.y = fmaxf(val.y, 0.f);
        val.z = fmaxf(val.z, 0.f); val.w = fmaxf(val.w, 0.f);
    }
    val.x = rtf(val.x); val.y = rtf(val.y); val.z = rtf(val.z); val.w = rtf(val.w);
    reinterpret_cast<float4*>(out)[(size_t)row*128 + threadIdx.x] = val;
}

// ---------------- fused: hcf row init + srms + relu + tf32 round ----------------
__global__ void posrms_kernel(const float* __restrict__ Wp, const float* __restrict__ bp,
                              float* __restrict__ out) {
    int n = blockIdx.x;
    int e = threadIdx.x * 4;
    float4 w = *reinterpret_cast<const float4*>(Wp + e);
    float4 b = *reinterpret_cast<const float4*>(bp + e);
    float fn = (float)n;
    float4 val;
    val.x = fn*w.x + b.x; val.y = fn*w.y + b.y; val.z = fn*w.z + b.z; val.w = fn*w.w + b.w;
    float ss = val.x*val.x + val.y*val.y + val.z*val.z + val.w*val.w;
    #pragma unroll
    for (int o = 16; o > 0; o >>= 1) ss += __shfl_xor_sync(0xffffffffu, ss, o);
    __shared__ float ws[4];
    if ((threadIdx.x & 31) == 0) ws[threadIdx.x >> 5] = ss;
    __syncthreads();
    float tot = ws[0] + ws[1] + ws[2] + ws[3];
    float inv = 1.0f / (sqrtf(tot * (1.0f/512.0f)) + 1e-8f);
    val.x = rtf(fmaxf(val.x*inv, 0.f)); val.y = rtf(fmaxf(val.y*inv, 0.f));
    val.z = rtf(fmaxf(val.z*inv, 0.f)); val.w = rtf(fmaxf(val.w*inv, 0.f));
    reinterpret_cast<float4*>(out)[(size_t)n*128 + threadIdx.x] = val;
}

// ---------------- fused transpose of all 7 weights: out[n][k] = tf32(in[k][n]) ----------------
__global__ void transpose_all_kernel(
    const float* __restrict__ Wu, const float* __restrict__ Wv, const float* __restrict__ Wo,
    const float* __restrict__ W1, const float* __restrict__ W2, const float* __restrict__ W3,
    const float* __restrict__ Wz)
{
    __shared__ float t[32][33];
    int z = blockIdx.z;
    const float* in; float* out; int K, N;
    switch (z) {
        case 0: in = Wu; out = g_WuvT;            K = DD;  N = DD1; break;
        case 1: in = Wv; out = g_WuvT + DD1*DD;   K = DD;  N = DD1; break;
        case 2: in = Wo; out = g_WoT;             K = DD1; N = DD;  break;
        case 3: in = W1; out = g_W1T;             K = EE;  N = EE;  break;
        case 4: in = W2; out = g_W2T;             K = EE;  N = EE;  break;
        case 5: in = W3; out = g_W3T;             K = EE;  N = EE;  break;
        default: in = Wz; out = g_WzT;            K = EE;  N = DD1; break;
    }
    if ((int)blockIdx.x * 32 >= N || (int)blockIdx.y * 32 >= K) return;
    int n0 = blockIdx.x * 32, k0 = blockIdx.y * 32;
    int tx = threadIdx.x, ty = threadIdx.y;   // 32 x 8
    #pragma unroll
    for (int i = 0; i < 32; i += 8)
        t[ty + i][tx] = rtf(in[(size_t)(k0 + ty + i) * N + n0 + tx]);
    __syncthreads();
    #pragma unroll
    for (int i = 0; i < 32; i += 8)
        out[(size_t)(n0 + ty + i) * K + k0 + tx] = t[tx][ty + i];
}

// ---------------- mma.sync tf32 GEMM, 128x128 tile, 2-stage cp.async ----------------
// act: 0 none, 1 silu ; smode: 0 plain; 3 +resid; 4 fused u|v
#define TGBK 32
#define TILEF (128*TGBK)
#define TG_SMEM (4*TILEF*4)       // 65536 bytes

__global__ void __launch_bounds__(256, 2) tgemm_kernel(
    const float* __restrict__ A, const float* __restrict__ Bt,
    const float* __restrict__ bias, const float* __restrict__ bias2,
    float* __restrict__ C,
    int M, int Nc, int K, int act, int smode, const float* __restrict__ resid)
{
    extern __shared__ float smf[];
    float* AsBase = smf;
    float* BsBase = smf + 2*TILEF;
    int tid = threadIdx.x;
    int wid = tid >> 5, lane = tid & 31;
    int gid = lane >> 2, tc = lane & 3;
    int m0 = (wid >> 2) * 64, n0 = (wid & 3) * 32;
    int bm = blockIdx.y * 128, bn = blockIdx.x * 128;

    float acc[4][4][4];
    #pragma unroll
    for (int mi = 0; mi < 4; mi++)
        #pragma unroll
        for (int ni = 0; ni < 4; ni++)
            #pragma unroll
            for (int q = 0; q < 4; q++) acc[mi][ni][q] = 0.f;

    const float* Abase = A  + (size_t)bm * K;
    const float* Bbase = Bt + (size_t)bn * K;

    #define LD_CHUNK(buf, k0v) do { \
        float* dA = AsBase + (buf)*TILEF; \
        float* dB = BsBase + (buf)*TILEF; \
        _Pragma("unroll") \
        for (int t_ = 0; t_ < 4; t_++) { \
            int j = tid + t_*256; \
            int row = j >> 3, c4 = j & 7; \
            int soff = row*32 + ((c4 ^ (row & 7)) << 2); \
            uint32_t da = smem_u32(dA + soff); \
            const float* sa = Abase + (size_t)row*K + (k0v) + (c4 << 2); \
            asm volatile("cp.async.cg.shared.global [%0], [%1], 16;" :: "r"(da), "l"(sa)); \
            uint32_t db = smem_u32(dB + soff); \
            const float* sb = Bbase + (size_t)row*K + (k0v) + (c4 << 2); \
            asm volatile("cp.async.cg.shared.global [%0], [%1], 16;" :: "r"(db), "l"(sb)); \
        } \
        asm volatile("cp.async.commit_group;"); \
    } while (0)

    int nch = K >> 5;
    LD_CHUNK(0, 0);
    for (int ch = 0; ch < nch; ch++) {
        if (ch + 1 < nch) {
            LD_CHUNK((ch + 1) & 1, (ch + 1) << 5);
            asm volatile("cp.async.wait_group 1;");
        } else {
            asm volatile("cp.async.wait_group 0;");
        }
        __syncthreads();
        const uint32_t* Au = (const uint32_t*)(AsBase + (ch & 1)*TILEF);
        const uint32_t* Bu = (const uint32_t*)(BsBase + (ch & 1)*TILEF);
        #pragma unroll
        for (int ks = 0; ks < 4; ks++) {
            int f0 = ks*2, f1 = f0 + 1;
            int x0 = (((f0 ^ gid) << 2) + tc);
            int x1 = (((f1 ^ gid) << 2) + tc);
            uint32_t af[4][4], bf[4][2];
            #pragma unroll
            for (int mi = 0; mi < 4; mi++) {
                int ra = (m0 + mi*16 + gid) * 32;
                int rb = ra + 8*32;
                af[mi][0] = Au[ra + x0]; af[mi][1] = Au[rb + x0];
                af[mi][2] = Au[ra + x1]; af[mi][3] = Au[rb + x1];
            }
            #pragma unroll
            for (int ni = 0; ni < 4; ni++) {
                int rn = (n0 + ni*8 + gid) * 32;
                bf[ni][0] = Bu[rn + x0];
                bf[ni][1] = Bu[rn + x1];
            }
            #pragma unroll
            for (int mi = 0; mi < 4; mi++)
                #pragma unroll
                for (int ni = 0; ni < 4; ni++)
                    mma_tf32(acc[mi][ni], af[mi], bf[ni]);
        }
        __syncthreads();
    }

    #pragma unroll
    for (int mi = 0; mi < 4; mi++) {
        #pragma unroll
        for (int ni = 0; ni < 4; ni++) {
            #pragma unroll
            for (int half = 0; half < 2; half++) {
                int r = bm + m0 + mi*16 + gid + half*8;
                int c = bn + n0 + ni*8 + 2*tc;
                float2 val = make_float2(acc[mi][ni][half*2], acc[mi][ni][half*2 + 1]);
                float2 bi;
                if (smode == 4 && c >= DD1) bi = *reinterpret_cast<const float2*>(bias2 + (c - DD1));
                else                        bi = *reinterpret_cast<const float2*>(bias + c);
                val.x += bi.x; val.y += bi.y;
                if (act == 1) {
                    val.x = silu_fast(val.x);
                    val.y = silu_fast(val.y);
                }
                if (smode == 0) {
                    *reinterpret_cast<float2*>(C + (size_t)r * Nc + c) = val;
                } else if (smode == 4) {
                    if (c < DD1) {
                        *reinterpret_cast<float2*>(&g_u[(size_t)r * DD1 + c]) = val;
                    } else {
                        int cc = c - DD1;
                        int b_ = r >> 11, nt = r & (NN - 1);
                        int h_ = cc >> 7, hd = cc & (HDD - 1);
                        *reinterpret_cast<float2*>(&g_v[(((size_t)(b_*HH + h_))*NN + nt)*HDD + hd]) = val;
                    }
                } else {
                    size_t o = (size_t)r * Nc + c;
                    float2 rr = *reinterpret_cast<const float2*>(resid + o);
                    val.x += rr.x; val.y += rr.y;
                    *reinterpret_cast<float2*>(C + o) = val;
                }
            }
        }
    }
}

// ---------------- mma.sync tf32 GEMM, 64x64 tile (small-M/N GEMMs) ----------------
// 8 warps, warp tile 16x32; smode: 0 plain; 2 coef->g_a decay. act always 0.
#define T64F (64*TGBK)                 // 2048 floats per op per stage
#define TG64_SMEM (4*T64F*4)           // 32768 bytes

__global__ void __launch_bounds__(256, 3) tgemm64_kernel(
    const float* __restrict__ A, const float* __restrict__ Bt,
    const float* __restrict__ bias, float* __restrict__ C,
    int M, int Nc, int K, int smode)
{
    extern __shared__ float smf[];
    float* AsBase = smf;
    float* BsBase = smf + 2*T64F;
    int tid = threadIdx.x;
    int wid = tid >> 5, lane = tid & 31;
    int gid = lane >> 2, tc = lane & 3;
    int m0 = (wid >> 1) * 16, n0 = (wid & 1) * 32;
    int bm = blockIdx.y * 64, bn = blockIdx.x * 64;

    float acc[4][4];
    #pragma unroll
    for (int ni = 0; ni < 4; ni++)
        #pragma unroll
        for (int q = 0; q < 4; q++) acc[ni][q] = 0.f;

    const float* Abase = A  + (size_t)bm * K;
    const float* Bbase = Bt + (size_t)bn * K;

    #define LD64(buf, k0v) do { \
        float* dA = AsBase + (buf)*T64F; \
        float* dB = BsBase + (buf)*T64F; \
        _Pragma("unroll") \
        for (int t_ = 0; t_ < 2; t_++) { \
            int j = tid + t_*256; \
            int row = j >> 3, c4 = j & 7; \
            int soff = row*32 + ((c4 ^ (row & 7)) << 2); \
            uint32_t da = smem_u32(dA + soff); \
            const float* sa = Abase + (size_t)row*K + (k0v) + (c4 << 2); \
            asm volatile("cp.async.cg.shared.global [%0], [%1], 16;" :: "r"(da), "l"(sa)); \
            uint32_t db = smem_u32(dB + soff); \
            const float* sb = Bbase + (size_t)row*K + (k0v) + (c4 << 2); \
            asm volatile("cp.async.cg.shared.global [%0], [%1], 16;" :: "r"(db), "l"(sb)); \
        } \
        asm volatile("cp.async.commit_group;"); \
    } while (0)

    int nch = K >> 5;
    LD64(0, 0);
    for (int ch = 0; ch < nch; ch++) {
        if (ch + 1 < nch) {
            LD64((ch + 1) & 1, (ch + 1) << 5);
            asm volatile("cp.async.wait_group 1;");
        } else {
            asm volatile("cp.async.wait_group 0;");
        }
        __syncthreads();
        const uint32_t* Au = (const uint32_t*)(AsBase + (ch & 1)*T64F);
        const uint32_t* Bu = (const uint32_t*)(BsBase + (ch & 1)*T64F);
        #pragma unroll
        for (int ks = 0; ks < 4; ks++) {
            int f0 = ks*2, f1 = f0 + 1;
            int x0 = (((f0 ^ gid) << 2) + tc);
            int x1 = (((f1 ^ gid) << 2) + tc);
            uint32_t af[4], bf[4][2];
            int ra = (m0 + gid) * 32;
            int rb = ra + 8*32;
            af[0] = Au[ra + x0]; af[1] = Au[rb + x0];
            af[2] = Au[ra + x1]; af[3] = Au[rb + x1];
            #pragma unroll
            for (int ni = 0; ni < 4; ni++) {
                int rn = (n0 + ni*8 + gid) * 32;
                bf[ni][0] = Bu[rn + x0];
                bf[ni][1] = Bu[rn + x1];
            }
            #pragma unroll
            for (int ni = 0; ni < 4; ni++)
                mma_tf32(acc[ni], af, bf[ni]);
        }
        __syncthreads();
    }

    #pragma unroll
    for (int ni = 0; ni < 4; ni++) {
        #pragma unroll
        for (int half = 0; half < 2; half++) {
            int r = bm + m0 + gid + half*8;
            int c = bn + n0 + ni*8 + 2*tc;
            float2 val = make_float2(acc[ni][half*2], acc[ni][half*2 + 1]);
            float2 bi = *reinterpret_cast<const float2*>(bias + c);
            val.x += bi.x; val.y += bi.y;
            if (smode == 2) {
                float sc = (r == 0) ? 1.0f : __expf((float)r * (-1.0005003335835335e-3f));
                int h_ = c >> 7, hd = c & (HDD - 1);
                val.x *= sc; val.y *= sc;
                *reinterpret_cast<float2*>(&g_a[((size_t)h_*NN + r)*HDD + hd]) = val;
            } else {
                *reinterpret_cast<float2*>(C + (size_t)r * Nc + c) = val;
            }
        }
    }
}

// ---------------- causal conv: a-ring + cp.async, unrolled steady-state loads ----------------
#define CSC 32
#define CTT 64
#define CONV_SMEM ((2*CSC*HDD + 128*HDD)*4)   // 98304 B

__global__ void __launch_bounds__(256, 2) conv_kernel(
    const float* __restrict__ vg, const float* __restrict__ ag,
    const float* __restrict__ ug, float* __restrict__ yg)
{
    extern __shared__ float sm[];
    float* v_sf = sm;                      // [2][CSC][HDD]
    float* a_sf = sm + 2*CSC*HDD;          // [128][HDD] ring, slot = k & 127
    float2* a_sh = reinterpret_cast<float2*>(a_sf);
    int bh = blockIdx.y;
    int b = bh >> 3, h = bh & 7;
    int t0 = (gridDim.x - 1 - blockIdx.x) * CTT;  // heavy tiles first
    int tid = threadIdx.x;
    int hdp = tid & 63;
    int tg  = tid >> 6;
    const float* vbase = vg + (size_t)bh * NN * HDD;
    const float* abase = ag + (size_t)h  * NN * HDD;
    float2 acc[16];
    #pragma unroll
    for (int i = 0; i < 16; i++) acc[i] = make_float2(0.f, 0.f);

    int nch = (t0 + CTT) / CSC;   // >= 2

    int vrow = tid >> 5;                   // 0..7 (row stride 8 over 4 unrolled iters)
    int vc4  = (tid & 31) << 2;

    #define ISSUE_V(c) do { \
        float* vdst = v_sf + ((c) & 1) * CSC * HDD; \
        const float* vsrc = vbase + (size_t)(c) * CSC * HDD; \
        _Pragma("unroll") \
        for (int i_ = 0; i_ < 4; i_++) { \
            int row = vrow + i_*8; \
            uint32_t dv = smem_u32(vdst + row*HDD + vc4); \
            asm volatile("cp.async.cg.shared.global [%0], [%1], 16;" :: "r"(dv), "l"(vsrc + row*HDD + vc4)); \
        } \
    } while (0)

    // steady-state: 32 new a rows, klo >= 0 guaranteed, branch-free
    #define ISSUE_A_FAST(c) do { \
        int klo_ = t0 - 32*(c) - 31; \
        const float* asrc = abase + (size_t)klo_*HDD; \
        _Pragma("unroll") \
        for (int i_ = 0; i_ < 4; i_++) { \
            int j_ = vrow + i_*8; \
            uint32_t da_ = smem_u32(a_sf + ((klo_ + j_) & 127)*HDD + vc4); \
            asm volatile("cp.async.cg.shared.global [%0], [%1], 16;" :: "r"(da_), "l"(asrc + (size_t)j_*HDD + vc4)); \
        } \
    } while (0)

    #define ISSUE_A_PRED(c, nrows_) do { \
        int klo_ = t0 - 32*(c) - 31; \
        for (int idx = tid; idx < (nrows_)*32; idx += 256) { \
            int j_ = idx >> 5, c4_ = (idx & 31) << 2; \
            int k_ = klo_ + j_; \
            uint32_t da_ = smem_u32(a_sf + (k_ & 127)*HDD + c4_); \
            if (k_ >= 0) { \
                asm volatile("cp.async.cg.shared.global [%0], [%1], 16;" :: "r"(da_), "l"(abase + (size_t)k_*HDD + c4_)); \
            } else { \
                asm volatile("st.shared.v4.b32 [%0], {%1,%1,%1,%1};" :: "r"(da_), "r"(0u)); \
            } \
        } \
    } while (0)

    // prologue: chunk 0 (95-row a window, predicated)
    ISSUE_V(0);
    ISSUE_A_PRED(0, 95);
    asm volatile("cp.async.commit_group;");

    for (int c = 0; c < nch; c++) {
        if (c + 1 < nch) {
            ISSUE_V(c + 1);
            if (c + 1 <= nch - 3) ISSUE_A_FAST(c + 1);
            else                  ISSUE_A_PRED(c + 1, 32);
            asm volatile("cp.async.commit_group;");
            asm volatile("cp.async.wait_group 1;");
        } else {
            asm volatile("cp.async.wait_group 0;");
        }
        __syncthreads();
        int s0 = c * CSC;
        const float2* vb = reinterpret_cast<const float2*>(v_sf + (c & 1)*CSC*HDD);
        #pragma unroll 1
        for (int sb = 0; sb < CSC; sb += 8) {
            float2 vr[8];
            #pragma unroll
            for (int q = 0; q < 8; q++) vr[q] = vb[(sb + q)*64 + hdp];
            int wk = t0 - s0 + tg*16 - sb - 7;
            float2 w[8];
            #pragma unroll
            for (int q = 0; q < 8; q++) w[q] = a_sh[((wk + q) & 127)*64 + hdp];
            #pragma unroll
            for (int tl = 0; tl < 16; tl++) {
                #pragma unroll
                for (int q = 0; q < 8; q++) fma2(acc[tl], w[q], vr[7 - q]);
                #pragma unroll
                for (int q = 0; q < 7; q++) w[q] = w[q + 1];
                w[7] = a_sh[((wk + tl + 8) & 127)*64 + hdp];
            }
        }
        __syncthreads();
    }
    #pragma unroll
    for (int tl = 0; tl < 16; tl++) {
        int t = t0 + tg*16 + tl;
        size_t o = ((size_t)(b*NN + t))*DD1 + h*HDD + hdp*2;
        float2 uu = *reinterpret_cast<const float2*>(ug + o);
        float2 r = acc[tl];
        r.x = rtf(r.x * uu.x); r.y = rtf(r.y * uu.y);
        *reinterpret_cast<float2*>(yg + o) = r;
    }
}

// ---------------- launch ----------------
extern "C" void kernel_launch(void* const* d_in, const int* in_sizes, int n_in,
                              void* d_out, int out_size)
{
    const float* x  = (const float*)d_in[0];
    const float* Wu = (const float*)d_in[1];
    const float* bu = (const float*)d_in[2];
    const float* Wv = (const float*)d_in[3];
    const float* bv = (const float*)d_in[4];
    const float* Wo = (const float*)d_in[5];
    const float* bo = (const float*)d_in[6];
    const float* Wp = (const float*)d_in[7];
    const float* bp = (const float*)d_in[8];
    const float* W1 = (const float*)d_in[9];
    const float* b1 = (const float*)d_in[10];
    const float* W2 = (const float*)d_in[11];
    const float* b2 = (const float*)d_in[12];
    const float* W3 = (const float*)d_in[13];
    const float* b3 = (const float*)d_in[14];
    const float* Wz = (const float*)d_in[15];
    const float* bz = (const float*)d_in[16];
    float* out = (float*)d_out;

    float *xn, *u, *v, *y, *h1, *t1, *a;
    float *wuvt, *wot, *w1t, *w2t, *w3t, *wzt;
    cudaGetSymbolAddress((void**)&xn, g_xn);
    cudaGetSymbolAddress((void**)&u,  g_u);
    cudaGetSymbolAddress((void**)&v,  g_v);
    cudaGetSymbolAddress((void**)&y,  g_y);
    cudaGetSymbolAddress((void**)&h1, g_h1);
    cudaGetSymbolAddress((void**)&t1, g_t1);
    cudaGetSymbolAddress((void**)&a,  g_a);
    cudaGetSymbolAddress((void**)&wuvt, g_WuvT);
    cudaGetSymbolAddress((void**)&wot, g_WoT);
    cudaGetSymbolAddress((void**)&w1t, g_W1T);
    cudaGetSymbolAddress((void**)&w2t, g_W2T);
    cudaGetSymbolAddress((void**)&w3t, g_W3T);
    cudaGetSymbolAddress((void**)&wzt, g_WzT);

    cudaFuncSetAttribute(conv_kernel,   cudaFuncAttributeMaxDynamicSharedMemorySize, CONV_SMEM);
    cudaFuncSetAttribute(tgemm_kernel,  cudaFuncAttributeMaxDynamicSharedMemorySize, TG_SMEM);
    cudaFuncSetAttribute(tgemm64_kernel, cudaFuncAttributeMaxDynamicSharedMemorySize, TG64_SMEM);

    // launch #1
    transpose_all_kernel<<<dim3(32, 32, 7), dim3(32, 8)>>>(Wu, Wv, Wo, W1, W2, W3, Wz);
    // launch #2
    rms_kernel<<<MROWS, 128>>>(x, xn, 0);
    // launch #3
    posrms_kernel<<<NN, 128>>>(Wp, bp, t1);
    // launch #4: fused u|v GEMM (profiled slot — control)
    tgemm_kernel<<<dim3(2*DD1/128, MROWS/128), 256, TG_SMEM>>>(xn, wuvt, bu, bv, nullptr, MROWS, 2*DD1, DD, 1, 4, nullptr);

    // pos-MLP on 64x64-tile GEMM (full SM coverage)
    tgemm64_kernel<<<dim3(EE/64, NN/64), 256, TG64_SMEM>>>(t1, w1t, b1, h1, NN, EE, EE, 0);
    rms_kernel<<<NN, 128>>>(h1, t1, 1);
    tgemm64_kernel<<<dim3(EE/64, NN/64), 256, TG64_SMEM>>>(t1, w2t, b2, h1, NN, EE, EE, 0);
    rms_kernel<<<NN, 128>>>(h1, t1, 1);
    tgemm64_kernel<<<dim3(EE/64, NN/64), 256, TG64_SMEM>>>(t1, w3t, b3, h1, NN, EE, EE, 0);
    rms_kernel<<<NN, 128>>>(h1, t1, 1);
    tgemm64_kernel<<<dim3(DD1/64, NN/64), 256, TG64_SMEM>>>(t1, wzt, bz, nullptr, NN, DD1, EE, 2);

    conv_kernel<<<dim3(NN/CTT, BB*HH), 256, CONV_SMEM>>>(v, a, u, y);

    tgemm_kernel<<<dim3(DD/128, MROWS/128), 256, TG_SMEM>>>(y, wot, bo, nullptr, out, MROWS, DD, DD1, 0, 3, x);
}